// round 15
// baseline (speedup 1.0000x reference)
#include <cuda_runtime.h>
#include <cuda_fp16.h>
#include <math.h>
#include <stdint.h>

#define B   32
#define N   100
#define H   256
#define HA  1024
#define HC  512
#define KA  5000
#define NN  10000
#define F   356
#define EF_BSTRIDE (101 * 356)
#define OUT_FILLED 320000

// ---------------- scratch ----------------
__device__ int    g_idx[B * KA];
__device__ float  g_base1[B * HA];
__device__ __half g_P1h[B * N * HA];
__device__ __half g_P2h[B * N * HA];
__device__ __half g_NOh[B * N * H];
__device__ __half g_W1th[HA * 512];
__device__ __half g_Y1h[(size_t)B * KA * HA];   // 327 MB fp16
__device__ __half g_W2th[HA * HA];
__device__ float  g_lpart[4][B * KA];           // partial logits per col-quarter

// ---------------- helpers ----------------
__device__ __forceinline__ uint32_t s2u(const void* p) {
    return (uint32_t)__cvta_generic_to_shared(p);
}
__device__ __forceinline__ float tanh_fast(float x) {
    float r;
    asm("tanh.approx.f32 %0, %1;" : "=f"(r) : "f"(x));
    return r;
}
#define CPA16(dst, src) asm volatile("cp.async.cg.shared.global [%0], [%1], 16;" :: "r"(dst), "l"(src) : "memory")
#define CPA_COMMIT()    asm volatile("cp.async.commit_group;" ::: "memory")
#define CPA_WAIT(n)     asm volatile("cp.async.wait_group %0;" :: "n"(n) : "memory")

#define LDSM4(r0, r1, r2, r3, a) \
    asm volatile("ldmatrix.sync.aligned.m8n8.x4.shared.b16 {%0,%1,%2,%3}, [%4];" \
        : "=r"(r0), "=r"(r1), "=r"(r2), "=r"(r3) : "r"(a))

__device__ __forceinline__ void mma_f16(float* c, const uint32_t* a, uint32_t b0, uint32_t b1) {
    asm volatile("mma.sync.aligned.m16n8k16.row.col.f32.f16.f16.f32 "
        "{%0,%1,%2,%3}, {%4,%5,%6,%7}, {%8,%9}, {%0,%1,%2,%3};"
        : "+f"(c[0]), "+f"(c[1]), "+f"(c[2]), "+f"(c[3])
        : "r"(a[0]), "r"(a[1]), "r"(a[2]), "r"(a[3]), "r"(b0), "r"(b1));
}

// ---------------- kernel 1: fused prep ----------------
#define NCH 313   // ceil(10000/32)
__global__ void k_prep(const float* __restrict__ ef,
                       const float* __restrict__ aW1,
                       const float* __restrict__ ab1,
                       const float* __restrict__ aW2) {
    __shared__ float sg[H];
    __shared__ float tt[32][33];
    __shared__ int scnt[320];
    int blk = blockIdx.x;
    int tid = threadIdx.x;

    if (blk < 32) {
        int b = blk;
        int lane = tid & 31;
        int w = tid >> 5;
        const float* base = ef + (size_t)b * EF_BSTRIDE;
        for (int c = w; c < NCH; c += 8) {
            int j = c * 32 + lane;
            bool act = false;
            if (j < NN) {
                int i = j / N;
                int cc = j - i * N;
                act = base[(size_t)(1 + i) * F + H + cc] > 0.5f;
            }
            unsigned m = __ballot_sync(0xffffffffu, act);
            if (lane == 0) scnt[c] = __popc(m);
        }
        __syncthreads();
        if (w == 0) {
            int run = 0;
            for (int g = 0; g < 10; g++) {
                int idx = g * 32 + lane;
                int orig = (idx < NCH) ? scnt[idx] : 0;
                int v = orig;
#pragma unroll
                for (int o = 1; o < 32; o <<= 1) {
                    int n = __shfl_up_sync(0xffffffffu, v, o);
                    if (lane >= o) v += n;
                }
                if (idx < NCH) scnt[idx] = run + v - orig;
                run += __shfl_sync(0xffffffffu, v, 31);
            }
        }
        __syncthreads();
        for (int c = w; c < NCH; c += 8) {
            int j = c * 32 + lane;
            bool act = false;
            if (j < NN) {
                int i = j / N;
                int cc = j - i * N;
                act = base[(size_t)(1 + i) * F + H + cc] > 0.5f;
            }
            unsigned m = __ballot_sync(0xffffffffu, act);
            if (act) {
                int pos = scnt[c] + __popc(m & ((1u << lane) - 1u));
                if (pos < KA) g_idx[b * KA + pos] = j;
            }
        }
    } else if (blk < 160) {
        int idx = blk - 32;
        int b = idx >> 2;
        int o = (idx & 3) * 256 + tid;
        if (tid < H) sg[tid] = ef[(size_t)b * EF_BSTRIDE + tid];
        __syncthreads();
        float acc = ab1[o];
#pragma unroll 8
        for (int h = 0; h < H; h++) acc += sg[h] * aW1[(size_t)h * HA + o];
        g_base1[b * HA + o] = acc;
    } else if (blk < 1184) {
        int bid = blk - 160;
        int bx = (bid & 31) * 32, by = (bid >> 5) * 32;
        int x = tid & 31, y = tid >> 5;   // 32 x 8
        for (int yy = y; yy < 32; yy += 8)
            tt[yy][x] = aW2[(size_t)(by + yy) * HA + bx + x];
        __syncthreads();
        for (int yy = y; yy < 32; yy += 8)
            g_W2th[(size_t)(bx + yy) * HA + by + x] = __float2half_rn(tt[x][yy]);
    } else if (blk < 1696) {
        int bid = blk - 1184;
        int kx = (bid & 15) * 32;
        int ny = (bid >> 4) * 32;
        int x = tid & 31, y = tid >> 5;
        for (int yy = y; yy < 32; yy += 8)
            tt[yy][x] = aW1[(size_t)(256 + kx + yy) * HA + ny + x];
        __syncthreads();
        for (int yy = y; yy < 32; yy += 8)
            g_W1th[(size_t)(ny + yy) * 512 + kx + x] = __float2half_rn(tt[x][yy]);
    } else {
        int bid = blk - 1696;
        for (int i = tid; i < 16 * H; i += 256) {
            int r = bid * 16 + (i >> 8);
            int c = i & 255;
            int b = r / N;
            int n = r - b * N;
            g_NOh[r * H + c] = __float2half_rn(ef[(size_t)b * EF_BSTRIDE + (size_t)(1 + n) * F + c]);
        }
    }
}

// ---------------- kernel 2: fp16 HMMA P1/P2 GEMM, 2-stage, 2 CTA/SM ----------------
#define PG_STG 46080
#define PG_SMEM (2 * PG_STG)
extern __shared__ __align__(128) unsigned char smraw[];

__global__ void __launch_bounds__(256, 2) k_pgemm_h() {
    const int tid = threadIdx.x;
    const int wid = tid >> 5;
    const int lane = tid & 31;
    const int wy = wid >> 2;
    const int wx = wid & 3;
    const int r0 = blockIdx.x * 64;
    const int c0 = blockIdx.y * 128;
    const uint32_t su = s2u(smraw);

    const int gq = lane >> 2;
    const int gt = lane & 3;

    auto issue = [&](int p) {
        const int k0 = p * 64;
        const uint32_t sb = su + (uint32_t)(p & 1) * PG_STG;
#pragma unroll
        for (int it = 0; it < 2; it++) {
            int idx = tid + it * 256;
            int row = idx >> 3, c = idx & 7;
            CPA16(sb + (uint32_t)(row * 144 + c * 16),
                  g_NOh + (size_t)(r0 + row) * H + k0 + c * 8);
        }
#pragma unroll
        for (int it = 0; it < 4; it++) {
            int idx = tid + it * 256;
            int row = idx >> 3, c = idx & 7;
            CPA16(sb + 9216 + (uint32_t)(row * 144 + c * 16),
                  g_W1th + (size_t)(c0 + row) * 512 + k0 + c * 8);
        }
#pragma unroll
        for (int it = 0; it < 4; it++) {
            int idx = tid + it * 256;
            int row = idx >> 3, c = idx & 7;
            CPA16(sb + 27648 + (uint32_t)(row * 144 + c * 16),
                  g_W1th + (size_t)(c0 + row) * 512 + 256 + k0 + c * 8);
        }
        CPA_COMMIT();
    };

    const uint32_t aw_off = (uint32_t)(wy * 32 * 144)
                          + (uint32_t)((lane & 15) * 144 + ((lane & 16) >> 4) * 16);
    const uint32_t bl = (uint32_t)(((lane & 7) + ((lane & 16) >> 1)) * 144 + ((lane & 8) >> 3) * 16);
    const uint32_t bwa_off = 9216  + (uint32_t)(wx * 32 * 144) + bl;
    const uint32_t bwb_off = 27648 + (uint32_t)(wx * 32 * 144) + bl;

    float acc1[2][4][4], acc2[2][4][4];
#pragma unroll
    for (int mt = 0; mt < 2; mt++)
#pragma unroll
        for (int nt = 0; nt < 4; nt++)
#pragma unroll
            for (int r = 0; r < 4; r++) { acc1[mt][nt][r] = 0.f; acc2[mt][nt][r] = 0.f; }

    issue(0);
    issue(1);

#pragma unroll
    for (int p = 0; p < 4; p++) {
        if (p < 3) { CPA_WAIT(1); } else { CPA_WAIT(0); }
        __syncthreads();
        const uint32_t sb = su + (uint32_t)(p & 1) * PG_STG;
#pragma unroll
        for (int k16 = 0; k16 < 4; k16++) {
            uint32_t af[2][4];
#pragma unroll
            for (int mt = 0; mt < 2; mt++)
                LDSM4(af[mt][0], af[mt][1], af[mt][2], af[mt][3],
                      sb + aw_off + mt * 16 * 144 + k16 * 32);
            uint32_t ba[2][4], bb[2][4];
#pragma unroll
            for (int q = 0; q < 2; q++) {
                LDSM4(ba[q][0], ba[q][1], ba[q][2], ba[q][3],
                      sb + bwa_off + q * 16 * 144 + k16 * 32);
                LDSM4(bb[q][0], bb[q][1], bb[q][2], bb[q][3],
                      sb + bwb_off + q * 16 * 144 + k16 * 32);
            }
#pragma unroll
            for (int mt = 0; mt < 2; mt++)
#pragma unroll
                for (int nt = 0; nt < 4; nt++) {
                    mma_f16(acc1[mt][nt], af[mt],
                            ba[nt >> 1][(nt & 1) * 2], ba[nt >> 1][(nt & 1) * 2 + 1]);
                    mma_f16(acc2[mt][nt], af[mt],
                            bb[nt >> 1][(nt & 1) * 2], bb[nt >> 1][(nt & 1) * 2 + 1]);
                }
        }
        if (p < 2) {
            __syncthreads();
            issue(p + 2);
        }
    }

#pragma unroll
    for (int mt = 0; mt < 2; mt++)
#pragma unroll
        for (int nt = 0; nt < 4; nt++)
#pragma unroll
            for (int rr = 0; rr < 2; rr++) {
                int row = r0 + wy * 32 + mt * 16 + rr * 8 + gq;
                int col = c0 + wx * 32 + nt * 8 + gt * 2;
                __half2 v1 = __floats2half2_rn(acc1[mt][nt][rr * 2], acc1[mt][nt][rr * 2 + 1]);
                __half2 v2 = __floats2half2_rn(acc2[mt][nt][rr * 2], acc2[mt][nt][rr * 2 + 1]);
                *(__half2*)&g_P1h[(size_t)row * HA + col] = v1;
                *(__half2*)&g_P2h[(size_t)row * HA + col] = v2;
            }
}

// ---------------- kernel 3: Y1h — one row per block, 128 threads, 16B/thread ----------------
__global__ void k_y1() {
    int row = blockIdx.x;
    int b = row / KA;
    int id = g_idx[row];
    int i1 = id / N;
    int i2 = id - i1 * N;
    int ch = threadIdx.x;
    uint4 u1 = ((const uint4*)(g_P1h + (size_t)(b * N + i1) * HA))[ch];
    uint4 u2 = ((const uint4*)(g_P2h + (size_t)(b * N + i2) * HA))[ch];
    const float4* bs = (const float4*)(g_base1 + (size_t)b * HA) + ch * 2;
    float4 d0 = bs[0];
    float4 d1 = bs[1];

    const __half2* h1p = (const __half2*)&u1;
    const __half2* h2p = (const __half2*)&u2;
    float base[8] = {d0.x, d0.y, d0.z, d0.w, d1.x, d1.y, d1.z, d1.w};

    uint4 outv;
    __half2* ho = (__half2*)&outv;
#pragma unroll
    for (int i = 0; i < 4; i++) {
        float2 a = __half22float2(h1p[i]);
        float2 c = __half22float2(h2p[i]);
        ho[i] = __floats2half2_rn(tanh_fast(a.x + c.x + base[2 * i]),
                                  tanh_fast(a.y + c.y + base[2 * i + 1]));
    }
    ((uint4*)(g_Y1h + (size_t)row * HA))[ch] = outv;
}

// ---------------- kernel 4: PERSISTENT fp16 HMMA layer2 GEMM + fused layer3 ----------------
// Grid = 296 (2 CTA/SM, all resident). Each CTA processes work items
// item = bid + j*296; item -> (row tile = item>>2, col quarter = item&3),
// 32 iterations per item. Globally flattened pipeline: prefetch crosses item
// boundaries, so the cp.async pipeline never drains between items.
// Intra-iteration schedule = proven round-10 optimum.
#define NSTG    3
#define STG_B   36864
#define OFFB_B  18432
#define NITEMS  5000
#define NPCTA   296
#define L23_SMEM (NSTG * STG_B + 2048)
extern __shared__ __align__(128) float smf[];

__global__ void __launch_bounds__(256, 2) k_l23(const float* __restrict__ ab2,
                                                const float* __restrict__ aW3) {
    const int tid = threadIdx.x;
    const int wid = tid >> 5;
    const int lane = tid & 31;
    const int wy = wid >> 2;
    const int wx = wid & 3;
    const int bid = blockIdx.x;

    float* sred = smf + (NSTG * STG_B) / 4;
    const uint32_t su = s2u(smf);

    const int gq = lane >> 2;
    const int gt = lane & 3;

    const uint32_t aw_off = (uint32_t)(wy * 64 * 144)
                          + (uint32_t)((lane & 15) * 144 + ((lane & 16) >> 4) * 16);
    const uint32_t bw_off = OFFB_B + (uint32_t)(wx * 32 * 144)
                          + (uint32_t)(((lane & 7) + ((lane & 16) >> 1)) * 144 + ((lane & 8) >> 3) * 16);

    const int n_items = (NITEMS - bid + NPCTA - 1) / NPCTA;
    const int TOT = n_items * 32;

    auto issue_A = [&](int p) {
        if (p < TOT) {
            const int item = bid + (p >> 5) * NPCTA;
            const size_t r0 = (size_t)(item >> 2) * 128;
            const int k0 = (p & 15) * 64;
            const uint32_t sb = su + (uint32_t)(p % NSTG) * STG_B;
            const __half* Ab = g_Y1h + r0 * HA + k0;
#pragma unroll
            for (int it = 0; it < 4; it++) {
                int idx = tid + it * 256;
                int row = idx >> 3, c = idx & 7;
                CPA16(sb + (uint32_t)(row * 144 + c * 16), Ab + (size_t)row * HA + c * 8);
            }
        }
    };
    auto issue_B = [&](int p) {
        if (p < TOT) {
            const int item = bid + (p >> 5) * NPCTA;
            const int q = item & 3;
            const int pct = q * 2 + ((p >> 4) & 1);
            const int k0 = (p & 15) * 64;
            const uint32_t sb = su + (uint32_t)(p % NSTG) * STG_B;
            const __half* Bb = g_W2th + (size_t)(pct * 128) * HA + k0;
#pragma unroll
            for (int it = 0; it < 4; it++) {
                int idx = tid + it * 256;
                int row = idx >> 3, c = idx & 7;
                CPA16(sb + OFFB_B + (uint32_t)(row * 144 + c * 16), Bb + (size_t)row * HA + c * 8);
            }
        }
        CPA_COMMIT();
    };

    float lsum[8];
#pragma unroll
    for (int i = 0; i < 8; i++) lsum[i] = 0.f;

    float acc[4][4][4];
#pragma unroll
    for (int mt = 0; mt < 4; mt++)
#pragma unroll
        for (int nt = 0; nt < 4; nt++)
#pragma unroll
            for (int r = 0; r < 4; r++) acc[mt][nt][r] = 0.f;

    issue_A(0); issue_B(0);
    issue_A(1); issue_B(1);

    for (int g = 0; g < TOT; g++) {
        CPA_WAIT(1);
        __syncthreads();

        const uint32_t sb = su + (uint32_t)(g % NSTG) * STG_B;
        const uint32_t sA = sb + aw_off;
        const uint32_t sB = sb + bw_off;

#pragma unroll
        for (int k16 = 0; k16 < 4; k16++) {
            uint32_t af[4][4];
#pragma unroll
            for (int mt = 0; mt < 4; mt++)
                LDSM4(af[mt][0], af[mt][1], af[mt][2], af[mt][3],
                      sA + mt * 16 * 144 + k16 * 32);
            uint32_t bf[2][4];
#pragma unroll
            for (int p = 0; p < 2; p++)
                LDSM4(bf[p][0], bf[p][1], bf[p][2], bf[p][3],
                      sB + p * 16 * 144 + k16 * 32);
#pragma unroll
            for (int mt = 0; mt < 4; mt++)
#pragma unroll
                for (int nt = 0; nt < 4; nt++)
                    mma_f16(acc[mt][nt], af[mt],
                            bf[nt >> 1][(nt & 1) * 2], bf[nt >> 1][(nt & 1) * 2 + 1]);
            if (k16 == 0) issue_A(g + 2);
            if (k16 == 1) issue_B(g + 2);
        }

        if ((g & 15) == 15) {
            const int item = bid + (g >> 5) * NPCTA;
            const int q = item & 3;
            const int ct = q * 2 + ((g >> 4) & 1);
#pragma unroll
            for (int mt = 0; mt < 4; mt++)
#pragma unroll
                for (int rr = 0; rr < 2; rr++) {
                    float v = 0.f;
#pragma unroll
                    for (int nt = 0; nt < 4; nt++) {
                        int col = ct * 128 + wx * 32 + nt * 8 + gt * 2;
                        float b2a = __ldg(ab2 + col);
                        float b2b = __ldg(ab2 + col + 1);
                        float w3a = __ldg(aW3 + col);
                        float w3b = __ldg(aW3 + col + 1);
                        float x0 = acc[mt][nt][rr * 2 + 0] + b2a;
                        float x1 = acc[mt][nt][rr * 2 + 1] + b2b;
                        v += tanh_fast(x0) * w3a + tanh_fast(x1) * w3b;
                    }
                    lsum[mt * 2 + rr] += v;
                }
#pragma unroll
            for (int mt = 0; mt < 4; mt++)
#pragma unroll
                for (int nt = 0; nt < 4; nt++)
#pragma unroll
                    for (int r = 0; r < 4; r++) acc[mt][nt][r] = 0.f;

            if ((g & 31) == 31) {
                // end of item: reduce lsum and store partial logits
                const size_t r0 = (size_t)(item >> 2) * 128;
#pragma unroll
                for (int i = 0; i < 8; i++) {
                    float v = lsum[i];
                    v += __shfl_xor_sync(0xffffffffu, v, 1);
                    v += __shfl_xor_sync(0xffffffffu, v, 2);
                    if (gt == 0) {
                        int lr = wy * 64 + (i >> 1) * 16 + (i & 1) * 8 + gq;
                        sred[wx * 128 + lr] = v;
                    }
                    lsum[i] = 0.f;
                }
                __syncthreads();
                if (tid < 128) {
                    float v = (sred[tid] + sred[128 + tid]) + (sred[256 + tid] + sred[384 + tid]);
                    g_lpart[q][r0 + tid] = v;
                }
                // sred reuse protected by the __syncthreads at top of next g
            }
        }
    }
}

// ---------------- kernel 5: softmax + zero + scatter + value head (fused) ----------------
__global__ void k_softmax(float* __restrict__ out, const float* __restrict__ ab3,
                          const float* __restrict__ ef,
                          const float* __restrict__ cW1, const float* __restrict__ cb1,
                          const float* __restrict__ cW2, const float* __restrict__ cb2,
                          const float* __restrict__ cW3, const float* __restrict__ cb3) {
    __shared__ float slog[KA];
    __shared__ float sred2[32];
    __shared__ float sbcast;
    __shared__ float sg[H];
    __shared__ float h1[HC];
    __shared__ float h2[HC];
    int b = blockIdx.x;
    int tid = threadIdx.x;  // 1024
    float b3 = ab3[0];

    for (int k = tid; k < NN; k += 1024)
        out[(size_t)b * NN + k] = 0.f;

    for (int k = tid; k < KA; k += 1024) {
        int row = b * KA + k;
        slog[k] = ((g_lpart[0][row] + g_lpart[1][row]) +
                   (g_lpart[2][row] + g_lpart[3][row])) + b3;
    }

    // ---- value head ----
    if (tid < H) sg[tid] = ef[(size_t)b * EF_BSTRIDE + tid];
    __syncthreads();
    if (tid < HC) {
        float acc = cb1[tid];
#pragma unroll 8
        for (int h = 0; h < H; h++) acc += sg[h] * cW1[h * HC + tid];
        h1[tid] = tanhf(acc);
    }
    __syncthreads();
    if (tid < HC) {
        float acc2 = cb2[tid];
#pragma unroll 8
        for (int h = 0; h < HC; h++) acc2 += h1[h] * cW2[h * HC + tid];
        h2[tid] = tanhf(acc2);
    }
    __syncthreads();
    {
        float p = (tid < HC) ? h2[tid] * cW3[tid] : 0.f;
#pragma unroll
        for (int o = 16; o; o >>= 1) p += __shfl_xor_sync(0xffffffffu, p, o);
        if ((tid & 31) == 0) sred2[tid >> 5] = p;
    }
    __syncthreads();
    if (tid < 32) {
        float v = (tid < 16) ? sred2[tid] : 0.f;
#pragma unroll
        for (int o = 16; o; o >>= 1) v += __shfl_xor_sync(0xffffffffu, v, o);
        if (tid == 0) out[OUT_FILLED + b] = v + cb3[0];
    }
    __syncthreads();

    // ---- softmax ----
    float m = -3.4e38f;
    for (int k = tid; k < KA; k += 1024) m = fmaxf(m, slog[k]);
#pragma unroll
    for (int o = 16; o; o >>= 1) m = fmaxf(m, __shfl_xor_sync(0xffffffffu, m, o));
    if ((tid & 31) == 0) sred2[tid >> 5] = m;
    __syncthreads();
    if (tid < 32) {
        float v = sred2[tid];
#pragma unroll
        for (int o = 16; o; o >>= 1) v = fmaxf(v, __shfl_xor_sync(0xffffffffu, v, o));
        if (tid == 0) sbcast = v;
    }
    __syncthreads();
    float gmax = sbcast;

    float s = 0.f;
    for (int k = tid; k < KA; k += 1024) s += expf(slog[k] - gmax);
#pragma unroll
    for (int o = 16; o; o >>= 1) s += __shfl_xor_sync(0xffffffffu, s, o);
    if ((tid & 31) == 0) sred2[tid >> 5] = s;
    __syncthreads();
    if (tid < 32) {
        float v = sred2[tid];
#pragma unroll
        for (int o = 16; o; o >>= 1) v += __shfl_xor_sync(0xffffffffu, v, o);
        if (tid == 0) sbcast = v;
    }
    __syncthreads();
    float inv = 1.0f / sbcast;

    for (int k = tid; k < KA; k += 1024) {
        int j = g_idx[b * KA + k];
        out[(size_t)b * NN + j] = expf(slog[k] - gmax) * inv;
    }
}

// ---------------- launch ----------------
extern "C" void kernel_launch(void* const* d_in, const int* in_sizes, int n_in,
                              void* d_out, int out_size) {
    const float* ef  = (const float*)d_in[0];
    const float* aW1 = (const float*)d_in[1];
    const float* ab1 = (const float*)d_in[2];
    const float* aW2 = (const float*)d_in[3];
    const float* ab2 = (const float*)d_in[4];
    const float* aW3 = (const float*)d_in[5];
    const float* ab3 = (const float*)d_in[6];
    const float* cW1 = (const float*)d_in[7];
    const float* cb1 = (const float*)d_in[8];
    const float* cW2 = (const float*)d_in[9];
    const float* cb2 = (const float*)d_in[10];
    const float* cW3 = (const float*)d_in[11];
    const float* cb3 = (const float*)d_in[12];
    float* out = (float*)d_out;

    cudaFuncSetAttribute(k_l23, cudaFuncAttributeMaxDynamicSharedMemorySize, L23_SMEM);
    cudaFuncSetAttribute(k_pgemm_h, cudaFuncAttributeMaxDynamicSharedMemorySize, PG_SMEM);

    k_prep<<<1896, 256>>>(ef, aW1, ab1, aW2);           // launch 1
    k_pgemm_h<<<dim3(50, 8), 256, PG_SMEM>>>();         // launch 2
    k_y1<<<B * KA, 128>>>();                            // launch 3
    k_l23<<<NPCTA, 256, L23_SMEM>>>(ab2, aW3);          // launch 4 (ncu capture)
    k_softmax<<<B, 1024>>>(out, ab3, ef, cW1, cb1, cW2, cb2, cW3, cb3);
}

// round 16
// speedup vs baseline: 1.0487x; 1.0487x over previous
#include <cuda_runtime.h>
#include <cuda_fp16.h>
#include <math.h>
#include <stdint.h>

#define B   32
#define N   100
#define H   256
#define HA  1024
#define HC  512
#define KA  5000
#define NN  10000
#define F   356
#define EF_BSTRIDE (101 * 356)
#define OUT_FILLED 320000

// ---------------- scratch ----------------
__device__ int    g_idx[B * KA];
__device__ float  g_base1[B * HA];
__device__ __half g_P1h[B * N * HA];
__device__ __half g_P2h[B * N * HA];
__device__ __half g_NOh[B * N * H];
__device__ __half g_W1th[HA * 512];
__device__ __half g_Y1h[(size_t)B * KA * HA];   // 327 MB fp16
__device__ __half g_W2th[HA * HA];
__device__ float  g_lpart[4][B * KA];           // partial logits per col-quarter

// ---------------- helpers ----------------
__device__ __forceinline__ uint32_t s2u(const void* p) {
    return (uint32_t)__cvta_generic_to_shared(p);
}
__device__ __forceinline__ float tanh_fast(float x) {
    float r;
    asm("tanh.approx.f32 %0, %1;" : "=f"(r) : "f"(x));
    return r;
}
#define CPA16(dst, src) asm volatile("cp.async.cg.shared.global [%0], [%1], 16;" :: "r"(dst), "l"(src) : "memory")
#define CPA_COMMIT()    asm volatile("cp.async.commit_group;" ::: "memory")
#define CPA_WAIT(n)     asm volatile("cp.async.wait_group %0;" :: "n"(n) : "memory")

#define LDSM4(r0, r1, r2, r3, a) \
    asm volatile("ldmatrix.sync.aligned.m8n8.x4.shared.b16 {%0,%1,%2,%3}, [%4];" \
        : "=r"(r0), "=r"(r1), "=r"(r2), "=r"(r3) : "r"(a))

__device__ __forceinline__ void mma_f16(float* c, const uint32_t* a, uint32_t b0, uint32_t b1) {
    asm volatile("mma.sync.aligned.m16n8k16.row.col.f32.f16.f16.f32 "
        "{%0,%1,%2,%3}, {%4,%5,%6,%7}, {%8,%9}, {%0,%1,%2,%3};"
        : "+f"(c[0]), "+f"(c[1]), "+f"(c[2]), "+f"(c[3])
        : "r"(a[0]), "r"(a[1]), "r"(a[2]), "r"(a[3]), "r"(b0), "r"(b1));
}

// ---------------- kernel 1: fused prep ----------------
#define NCH 313   // ceil(10000/32)
__global__ void k_prep(const float* __restrict__ ef,
                       const float* __restrict__ aW1,
                       const float* __restrict__ ab1,
                       const float* __restrict__ aW2) {
    __shared__ float sg[H];
    __shared__ float tt[32][33];
    __shared__ int scnt[320];
    int blk = blockIdx.x;
    int tid = threadIdx.x;

    if (blk < 32) {
        int b = blk;
        int lane = tid & 31;
        int w = tid >> 5;
        const float* base = ef + (size_t)b * EF_BSTRIDE;
        for (int c = w; c < NCH; c += 8) {
            int j = c * 32 + lane;
            bool act = false;
            if (j < NN) {
                int i = j / N;
                int cc = j - i * N;
                act = base[(size_t)(1 + i) * F + H + cc] > 0.5f;
            }
            unsigned m = __ballot_sync(0xffffffffu, act);
            if (lane == 0) scnt[c] = __popc(m);
        }
        __syncthreads();
        if (w == 0) {
            int run = 0;
            for (int g = 0; g < 10; g++) {
                int idx = g * 32 + lane;
                int orig = (idx < NCH) ? scnt[idx] : 0;
                int v = orig;
#pragma unroll
                for (int o = 1; o < 32; o <<= 1) {
                    int n = __shfl_up_sync(0xffffffffu, v, o);
                    if (lane >= o) v += n;
                }
                if (idx < NCH) scnt[idx] = run + v - orig;
                run += __shfl_sync(0xffffffffu, v, 31);
            }
        }
        __syncthreads();
        for (int c = w; c < NCH; c += 8) {
            int j = c * 32 + lane;
            bool act = false;
            if (j < NN) {
                int i = j / N;
                int cc = j - i * N;
                act = base[(size_t)(1 + i) * F + H + cc] > 0.5f;
            }
            unsigned m = __ballot_sync(0xffffffffu, act);
            if (act) {
                int pos = scnt[c] + __popc(m & ((1u << lane) - 1u));
                if (pos < KA) g_idx[b * KA + pos] = j;
            }
        }
    } else if (blk < 160) {
        int idx = blk - 32;
        int b = idx >> 2;
        int o = (idx & 3) * 256 + tid;
        if (tid < H) sg[tid] = ef[(size_t)b * EF_BSTRIDE + tid];
        __syncthreads();
        float acc = ab1[o];
#pragma unroll 8
        for (int h = 0; h < H; h++) acc += sg[h] * aW1[(size_t)h * HA + o];
        g_base1[b * HA + o] = acc;
    } else if (blk < 1184) {
        int bid = blk - 160;
        int bx = (bid & 31) * 32, by = (bid >> 5) * 32;
        int x = tid & 31, y = tid >> 5;   // 32 x 8
        for (int yy = y; yy < 32; yy += 8)
            tt[yy][x] = aW2[(size_t)(by + yy) * HA + bx + x];
        __syncthreads();
        for (int yy = y; yy < 32; yy += 8)
            g_W2th[(size_t)(bx + yy) * HA + by + x] = __float2half_rn(tt[x][yy]);
    } else if (blk < 1696) {
        int bid = blk - 1184;
        int kx = (bid & 15) * 32;
        int ny = (bid >> 4) * 32;
        int x = tid & 31, y = tid >> 5;
        for (int yy = y; yy < 32; yy += 8)
            tt[yy][x] = aW1[(size_t)(256 + kx + yy) * HA + ny + x];
        __syncthreads();
        for (int yy = y; yy < 32; yy += 8)
            g_W1th[(size_t)(ny + yy) * 512 + kx + x] = __float2half_rn(tt[x][yy]);
    } else {
        int bid = blk - 1696;
        for (int i = tid; i < 16 * H; i += 256) {
            int r = bid * 16 + (i >> 8);
            int c = i & 255;
            int b = r / N;
            int n = r - b * N;
            g_NOh[r * H + c] = __float2half_rn(ef[(size_t)b * EF_BSTRIDE + (size_t)(1 + n) * F + c]);
        }
    }
}

// ---------------- kernel 2: fp16 HMMA P1/P2 GEMM, 2-stage, 2 CTA/SM ----------------
#define PG_STG 46080
#define PG_SMEM (2 * PG_STG)
extern __shared__ __align__(128) unsigned char smraw[];

__global__ void __launch_bounds__(256, 2) k_pgemm_h() {
    const int tid = threadIdx.x;
    const int wid = tid >> 5;
    const int lane = tid & 31;
    const int wy = wid >> 2;
    const int wx = wid & 3;
    const int r0 = blockIdx.x * 64;
    const int c0 = blockIdx.y * 128;
    const uint32_t su = s2u(smraw);

    const int gq = lane >> 2;
    const int gt = lane & 3;

    auto issue = [&](int p) {
        const int k0 = p * 64;
        const uint32_t sb = su + (uint32_t)(p & 1) * PG_STG;
#pragma unroll
        for (int it = 0; it < 2; it++) {
            int idx = tid + it * 256;
            int row = idx >> 3, c = idx & 7;
            CPA16(sb + (uint32_t)(row * 144 + c * 16),
                  g_NOh + (size_t)(r0 + row) * H + k0 + c * 8);
        }
#pragma unroll
        for (int it = 0; it < 4; it++) {
            int idx = tid + it * 256;
            int row = idx >> 3, c = idx & 7;
            CPA16(sb + 9216 + (uint32_t)(row * 144 + c * 16),
                  g_W1th + (size_t)(c0 + row) * 512 + k0 + c * 8);
        }
#pragma unroll
        for (int it = 0; it < 4; it++) {
            int idx = tid + it * 256;
            int row = idx >> 3, c = idx & 7;
            CPA16(sb + 27648 + (uint32_t)(row * 144 + c * 16),
                  g_W1th + (size_t)(c0 + row) * 512 + 256 + k0 + c * 8);
        }
        CPA_COMMIT();
    };

    const uint32_t aw_off = (uint32_t)(wy * 32 * 144)
                          + (uint32_t)((lane & 15) * 144 + ((lane & 16) >> 4) * 16);
    const uint32_t bl = (uint32_t)(((lane & 7) + ((lane & 16) >> 1)) * 144 + ((lane & 8) >> 3) * 16);
    const uint32_t bwa_off = 9216  + (uint32_t)(wx * 32 * 144) + bl;
    const uint32_t bwb_off = 27648 + (uint32_t)(wx * 32 * 144) + bl;

    float acc1[2][4][4], acc2[2][4][4];
#pragma unroll
    for (int mt = 0; mt < 2; mt++)
#pragma unroll
        for (int nt = 0; nt < 4; nt++)
#pragma unroll
            for (int r = 0; r < 4; r++) { acc1[mt][nt][r] = 0.f; acc2[mt][nt][r] = 0.f; }

    issue(0);
    issue(1);

#pragma unroll
    for (int p = 0; p < 4; p++) {
        if (p < 3) { CPA_WAIT(1); } else { CPA_WAIT(0); }
        __syncthreads();
        const uint32_t sb = su + (uint32_t)(p & 1) * PG_STG;
#pragma unroll
        for (int k16 = 0; k16 < 4; k16++) {
            uint32_t af[2][4];
#pragma unroll
            for (int mt = 0; mt < 2; mt++)
                LDSM4(af[mt][0], af[mt][1], af[mt][2], af[mt][3],
                      sb + aw_off + mt * 16 * 144 + k16 * 32);
            uint32_t ba[2][4], bb[2][4];
#pragma unroll
            for (int q = 0; q < 2; q++) {
                LDSM4(ba[q][0], ba[q][1], ba[q][2], ba[q][3],
                      sb + bwa_off + q * 16 * 144 + k16 * 32);
                LDSM4(bb[q][0], bb[q][1], bb[q][2], bb[q][3],
                      sb + bwb_off + q * 16 * 144 + k16 * 32);
            }
#pragma unroll
            for (int mt = 0; mt < 2; mt++)
#pragma unroll
                for (int nt = 0; nt < 4; nt++) {
                    mma_f16(acc1[mt][nt], af[mt],
                            ba[nt >> 1][(nt & 1) * 2], ba[nt >> 1][(nt & 1) * 2 + 1]);
                    mma_f16(acc2[mt][nt], af[mt],
                            bb[nt >> 1][(nt & 1) * 2], bb[nt >> 1][(nt & 1) * 2 + 1]);
                }
        }
        if (p < 2) {
            __syncthreads();
            issue(p + 2);
        }
    }

#pragma unroll
    for (int mt = 0; mt < 2; mt++)
#pragma unroll
        for (int nt = 0; nt < 4; nt++)
#pragma unroll
            for (int rr = 0; rr < 2; rr++) {
                int row = r0 + wy * 32 + mt * 16 + rr * 8 + gq;
                int col = c0 + wx * 32 + nt * 8 + gt * 2;
                __half2 v1 = __floats2half2_rn(acc1[mt][nt][rr * 2], acc1[mt][nt][rr * 2 + 1]);
                __half2 v2 = __floats2half2_rn(acc2[mt][nt][rr * 2], acc2[mt][nt][rr * 2 + 1]);
                *(__half2*)&g_P1h[(size_t)row * HA + col] = v1;
                *(__half2*)&g_P2h[(size_t)row * HA + col] = v2;
            }
}

// ---------------- kernel 3: Y1h — one row per block, 128 threads, 16B/thread ----------------
__global__ void k_y1() {
    int row = blockIdx.x;
    int b = row / KA;
    int id = g_idx[row];
    int i1 = id / N;
    int i2 = id - i1 * N;
    int ch = threadIdx.x;
    uint4 u1 = ((const uint4*)(g_P1h + (size_t)(b * N + i1) * HA))[ch];
    uint4 u2 = ((const uint4*)(g_P2h + (size_t)(b * N + i2) * HA))[ch];
    const float4* bs = (const float4*)(g_base1 + (size_t)b * HA) + ch * 2;
    float4 d0 = bs[0];
    float4 d1 = bs[1];

    const __half2* h1p = (const __half2*)&u1;
    const __half2* h2p = (const __half2*)&u2;
    float base[8] = {d0.x, d0.y, d0.z, d0.w, d1.x, d1.y, d1.z, d1.w};

    uint4 outv;
    __half2* ho = (__half2*)&outv;
#pragma unroll
    for (int i = 0; i < 4; i++) {
        float2 a = __half22float2(h1p[i]);
        float2 c = __half22float2(h2p[i]);
        ho[i] = __floats2half2_rn(tanh_fast(a.x + c.x + base[2 * i]),
                                  tanh_fast(a.y + c.y + base[2 * i + 1]));
    }
    ((uint4*)(g_Y1h + (size_t)row * HA))[ch] = outv;
}

// ---------------- kernel 4: fp16 HMMA layer2 GEMM + fused layer3 (round-14) ----------------
// Grid 5000: each CTA = 128 rows x 256-col quarter (2 col-tiles, NIT=32).
// Round-10 producer schedule. Partial logits -> g_lpart[q].
#define NSTG    3
#define STG_B   36864
#define OFFB_B  18432
#define NIT     32
#define L23_SMEM (NSTG * STG_B + 2048)
extern __shared__ __align__(128) float smf[];

__global__ void __launch_bounds__(256, 2) k_l23(const float* __restrict__ ab2,
                                                const float* __restrict__ aW3) {
    const int tid = threadIdx.x;
    const int wid = tid >> 5;
    const int lane = tid & 31;
    const int wy = wid >> 2;
    const int wx = wid & 3;
    const int q = blockIdx.x & 3;
    const size_t r0 = (size_t)(blockIdx.x >> 2) * 128;

    float* sred = smf + (NSTG * STG_B) / 4;
    const uint32_t su = s2u(smf);

    const int gq = lane >> 2;
    const int gt = lane & 3;

    const uint32_t aw_off = (uint32_t)(wy * 64 * 144)
                          + (uint32_t)((lane & 15) * 144 + ((lane & 16) >> 4) * 16);
    const uint32_t bw_off = OFFB_B + (uint32_t)(wx * 32 * 144)
                          + (uint32_t)(((lane & 7) + ((lane & 16) >> 1)) * 144 + ((lane & 8) >> 3) * 16);

    const __half* Ybase = g_Y1h + r0 * HA;

    auto issue_A = [&](int p) {
        if (p < NIT) {
            const int k0 = (p & 15) * 64;
            const uint32_t sb = su + (uint32_t)(p % NSTG) * STG_B;
            const __half* Ab = Ybase + k0;
#pragma unroll
            for (int it = 0; it < 4; it++) {
                int idx = tid + it * 256;
                int row = idx >> 3, c = idx & 7;
                CPA16(sb + (uint32_t)(row * 144 + c * 16), Ab + (size_t)row * HA + c * 8);
            }
        }
    };
    auto issue_B = [&](int p) {
        if (p < NIT) {
            const int pct = q * 2 + (p >> 4);
            const int k0 = (p & 15) * 64;
            const uint32_t sb = su + (uint32_t)(p % NSTG) * STG_B;
            const __half* Bb = g_W2th + (size_t)(pct * 128) * HA + k0;
#pragma unroll
            for (int it = 0; it < 4; it++) {
                int idx = tid + it * 256;
                int row = idx >> 3, c = idx & 7;
                CPA16(sb + OFFB_B + (uint32_t)(row * 144 + c * 16), Bb + (size_t)row * HA + c * 8);
            }
        }
        CPA_COMMIT();
    };

    float lsum[8];
#pragma unroll
    for (int i = 0; i < 8; i++) lsum[i] = 0.f;

    float acc[4][4][4];
#pragma unroll
    for (int mt = 0; mt < 4; mt++)
#pragma unroll
        for (int nt = 0; nt < 4; nt++)
#pragma unroll
            for (int r = 0; r < 4; r++) acc[mt][nt][r] = 0.f;

    issue_A(0); issue_B(0);
    issue_A(1); issue_B(1);

    for (int it = 0; it < NIT; it++) {
        CPA_WAIT(1);
        __syncthreads();

        const uint32_t sb = su + (uint32_t)(it % NSTG) * STG_B;
        const uint32_t sA = sb + aw_off;
        const uint32_t sB = sb + bw_off;

#pragma unroll
        for (int k16 = 0; k16 < 4; k16++) {
            uint32_t af[4][4];
#pragma unroll
            for (int mt = 0; mt < 4; mt++)
                LDSM4(af[mt][0], af[mt][1], af[mt][2], af[mt][3],
                      sA + mt * 16 * 144 + k16 * 32);
            uint32_t bf[2][4];
#pragma unroll
            for (int p = 0; p < 2; p++)
                LDSM4(bf[p][0], bf[p][1], bf[p][2], bf[p][3],
                      sB + p * 16 * 144 + k16 * 32);
#pragma unroll
            for (int mt = 0; mt < 4; mt++)
#pragma unroll
                for (int nt = 0; nt < 4; nt++)
                    mma_f16(acc[mt][nt], af[mt],
                            bf[nt >> 1][(nt & 1) * 2], bf[nt >> 1][(nt & 1) * 2 + 1]);
            if (k16 == 0) issue_A(it + 2);
            if (k16 == 1) issue_B(it + 2);
        }

        if ((it & 15) == 15) {
            const int ct = q * 2 + (it >> 4);
#pragma unroll
            for (int mt = 0; mt < 4; mt++)
#pragma unroll
                for (int rr = 0; rr < 2; rr++) {
                    float v = 0.f;
#pragma unroll
                    for (int nt = 0; nt < 4; nt++) {
                        int col = ct * 128 + wx * 32 + nt * 8 + gt * 2;
                        float b2a = __ldg(ab2 + col);
                        float b2b = __ldg(ab2 + col + 1);
                        float w3a = __ldg(aW3 + col);
                        float w3b = __ldg(aW3 + col + 1);
                        float x0 = acc[mt][nt][rr * 2 + 0] + b2a;
                        float x1 = acc[mt][nt][rr * 2 + 1] + b2b;
                        v += tanh_fast(x0) * w3a + tanh_fast(x1) * w3b;
                    }
                    lsum[mt * 2 + rr] += v;
                }
#pragma unroll
            for (int mt = 0; mt < 4; mt++)
#pragma unroll
                for (int nt = 0; nt < 4; nt++)
#pragma unroll
                    for (int r = 0; r < 4; r++) acc[mt][nt][r] = 0.f;
        }
    }

#pragma unroll
    for (int i = 0; i < 8; i++) {
        float v = lsum[i];
        v += __shfl_xor_sync(0xffffffffu, v, 1);
        v += __shfl_xor_sync(0xffffffffu, v, 2);
        if (gt == 0) {
            int lr = wy * 64 + (i >> 1) * 16 + (i & 1) * 8 + gq;
            sred[wx * 128 + lr] = v;
        }
    }
    __syncthreads();
    if (tid < 128) {
        float v = (sred[tid] + sred[128 + tid]) + (sred[256 + tid] + sred[384 + tid]);
        g_lpart[q][r0 + tid] = v;
    }
}

// ---------------- kernel 5: softmax + zero + scatter + value head (fused) ----------------
__global__ void k_softmax(float* __restrict__ out, const float* __restrict__ ab3,
                          const float* __restrict__ ef,
                          const float* __restrict__ cW1, const float* __restrict__ cb1,
                          const float* __restrict__ cW2, const float* __restrict__ cb2,
                          const float* __restrict__ cW3, const float* __restrict__ cb3) {
    __shared__ float slog[KA];
    __shared__ float sred2[32];
    __shared__ float sbcast;
    __shared__ float sg[H];
    __shared__ float h1[HC];
    __shared__ float h2[HC];
    int b = blockIdx.x;
    int tid = threadIdx.x;  // 1024
    float b3 = ab3[0];

    // zero this batch's filled row (float4)
    {
        float4* o4 = (float4*)(out + (size_t)b * NN);
        for (int k = tid; k < NN / 4; k += 1024)
            o4[k] = make_float4(0.f, 0.f, 0.f, 0.f);
    }

    for (int k = tid; k < KA; k += 1024) {
        int row = b * KA + k;
        slog[k] = ((g_lpart[0][row] + g_lpart[1][row]) +
                   (g_lpart[2][row] + g_lpart[3][row])) + b3;
    }

    // ---- value head ----
    if (tid < H) sg[tid] = ef[(size_t)b * EF_BSTRIDE + tid];
    __syncthreads();
    if (tid < HC) {
        float acc = cb1[tid];
#pragma unroll 8
        for (int h = 0; h < H; h++) acc += sg[h] * cW1[h * HC + tid];
        h1[tid] = tanhf(acc);
    }
    __syncthreads();
    if (tid < HC) {
        float acc2 = cb2[tid];
#pragma unroll 8
        for (int h = 0; h < HC; h++) acc2 += h1[h] * cW2[h * HC + tid];
        h2[tid] = tanhf(acc2);
    }
    __syncthreads();
    {
        float p = (tid < HC) ? h2[tid] * cW3[tid] : 0.f;
#pragma unroll
        for (int o = 16; o; o >>= 1) p += __shfl_xor_sync(0xffffffffu, p, o);
        if ((tid & 31) == 0) sred2[tid >> 5] = p;
    }
    __syncthreads();
    if (tid < 32) {
        float v = (tid < 16) ? sred2[tid] : 0.f;
#pragma unroll
        for (int o = 16; o; o >>= 1) v += __shfl_xor_sync(0xffffffffu, v, o);
        if (tid == 0) out[OUT_FILLED + b] = v + cb3[0];
    }
    __syncthreads();

    // ---- softmax ----
    float m = -3.4e38f;
    for (int k = tid; k < KA; k += 1024) m = fmaxf(m, slog[k]);
#pragma unroll
    for (int o = 16; o; o >>= 1) m = fmaxf(m, __shfl_xor_sync(0xffffffffu, m, o));
    if ((tid & 31) == 0) sred2[tid >> 5] = m;
    __syncthreads();
    if (tid < 32) {
        float v = sred2[tid];
#pragma unroll
        for (int o = 16; o; o >>= 1) v = fmaxf(v, __shfl_xor_sync(0xffffffffu, v, o));
        if (tid == 0) sbcast = v;
    }
    __syncthreads();
    float gmax = sbcast;

    // sum pass caches exp back into slog
    float s = 0.f;
    for (int k = tid; k < KA; k += 1024) {
        float e = expf(slog[k] - gmax);
        slog[k] = e;
        s += e;
    }
#pragma unroll
    for (int o = 16; o; o >>= 1) s += __shfl_xor_sync(0xffffffffu, s, o);
    if ((tid & 31) == 0) sred2[tid >> 5] = s;
    __syncthreads();
    if (tid < 32) {
        float v = sred2[tid];
#pragma unroll
        for (int o = 16; o; o >>= 1) v += __shfl_xor_sync(0xffffffffu, v, o);
        if (tid == 0) sbcast = v;
    }
    __syncthreads();
    float inv = 1.0f / sbcast;

    for (int k = tid; k < KA; k += 1024) {
        int j = g_idx[b * KA + k];
        out[(size_t)b * NN + j] = slog[k] * inv;
    }
}

// ---------------- launch ----------------
extern "C" void kernel_launch(void* const* d_in, const int* in_sizes, int n_in,
                              void* d_out, int out_size) {
    const float* ef  = (const float*)d_in[0];
    const float* aW1 = (const float*)d_in[1];
    const float* ab1 = (const float*)d_in[2];
    const float* aW2 = (const float*)d_in[3];
    const float* ab2 = (const float*)d_in[4];
    const float* aW3 = (const float*)d_in[5];
    const float* ab3 = (const float*)d_in[6];
    const float* cW1 = (const float*)d_in[7];
    const float* cb1 = (const float*)d_in[8];
    const float* cW2 = (const float*)d_in[9];
    const float* cb2 = (const float*)d_in[10];
    const float* cW3 = (const float*)d_in[11];
    const float* cb3 = (const float*)d_in[12];
    float* out = (float*)d_out;

    cudaFuncSetAttribute(k_l23, cudaFuncAttributeMaxDynamicSharedMemorySize, L23_SMEM);
    cudaFuncSetAttribute(k_pgemm_h, cudaFuncAttributeMaxDynamicSharedMemorySize, PG_SMEM);

    k_prep<<<1896, 256>>>(ef, aW1, ab1, aW2);           // launch 1
    k_pgemm_h<<<dim3(50, 8), 256, PG_SMEM>>>();         // launch 2
    k_y1<<<B * KA, 128>>>();                            // launch 3
    k_l23<<<5000, 256, L23_SMEM>>>(ab2, aW3);           // launch 4 (ncu capture)
    k_softmax<<<B, 1024>>>(out, ab3, ef, cW1, cb1, cW2, cb2, cW3, cb3);
}